// round 9
// baseline (speedup 1.0000x reference)
#include <cuda_runtime.h>

// Problem constants
#define YY 5
#define NN 200000
#define GG 128
#define II 128
#define RR 3
#define BB 1024
#define KK 64
#define KTOT (RR * GG)   // 384

#define NWEFF_BLK 192    // weff-builder CTAs prepended to gather grid
#define NSPLIT 4         // GEMM K-split factor
#define MTOT (YY * BB)   // 5120
#define NTILE (MTOT / 32)  // 160 row tiles

// Scratch (no cudaMalloc allowed)
__device__ __align__(16) float g_mean[(size_t)MTOT * KTOT];        // [m][k]
__device__ __align__(16) float g_weff[KTOT * II];                  // [k][i]
__device__ __align__(16) float g_part[NSPLIT][(size_t)MTOT * II];  // partials
__device__ int g_sem[NTILE];                                       // split-k counters

// ---------------------------------------------------------------------------
// Fused kernel #1 (1D grid, 256 threads):
//   blocks [0, 192):  build g_weff; block 0 also zeroes split-k semaphores
//   blocks [192, 192+1920): gather + masked mean, one WARP per (y, r, b)
// Warp-per-task gather: lane owns g-columns lane*4..+3 (float4); indices in
// a per-warp smem buffer; no cross-lane reduction, no block syncs.
// int64-vs-int32 detection per-warp from first 64 words of counts (L1 hits).
// ---------------------------------------------------------------------------
__global__ void __launch_bounds__(256) gather_mean_kernel(
        const float* __restrict__ emb,
        const void* __restrict__ nbr,
        const void* __restrict__ cnt,
        const float* __restrict__ Wrel,
        const float* __restrict__ Wcite) {
    const int bid = blockIdx.x;
    const int tid = threadIdx.x;

    if (bid < NWEFF_BLK) {
        if (bid == 0 && tid < NTILE) g_sem[tid] = 0;
        int idx = bid * 256 + tid;   // < 49152
        int r  = idx / (GG * II);
        int gi = idx - r * (GG * II);
        float v;
        if (r == 0)
            v = Wcite[gi] + Wcite[GG * II + gi] + Wcite[2 * GG * II + gi];
        else
            v = Wrel[idx];
        g_weff[idx] = v;
        return;
    }

    const int wid  = tid >> 5;           // warp in CTA 0..7
    const int lane = tid & 31;
    const int task = (bid - NWEFF_BLK) * 8 + wid;   // 0..15359
    const int y   = task / (RR * BB);
    const int rem = task - y * (RR * BB);
    const int r   = rem >> 10;
    const int b   = rem & (BB - 1);

    __shared__ __align__(16) int sidx[8][KK];

    // dtype detection (per warp, redundant but L1-hot): odd words of first
    // 32 int64 candidates of counts are all zero iff int64.
    unsigned int v = ((const unsigned int*)cnt)[2 * lane + 1];
    const int is64 = (__ballot_sync(0xffffffffu, v != 0u) == 0u) ? 1 : 0;

    const long long lin = ((long long)y * RR + r) * BB + b;

    int count;
    if (is64) {
        count = (int)((const long long*)cnt)[lin];
        sidx[wid][lane]      = (int)((const long long*)nbr)[lin * KK + lane];
        sidx[wid][lane + 32] = (int)((const long long*)nbr)[lin * KK + lane + 32];
    } else {
        count = ((const int*)cnt)[lin];
        sidx[wid][lane]      = ((const int*)nbr)[lin * KK + lane];
        sidx[wid][lane + 32] = ((const int*)nbr)[lin * KK + lane + 32];
    }
    __syncwarp();

    // float4 view of this year's embedding slab; row stride = 32 float4s
    const float4* e = (const float4*)(emb + (size_t)y * NN * GG) + lane;

    float4 acc = make_float4(0.f, 0.f, 0.f, 0.f);
    int k = 0;
    for (; k + 4 <= count; k += 4) {
        int i0 = sidx[wid][k + 0];
        int i1 = sidx[wid][k + 1];
        int i2 = sidx[wid][k + 2];
        int i3 = sidx[wid][k + 3];
        float4 v0 = e[(size_t)i0 * 32];
        float4 v1 = e[(size_t)i1 * 32];
        float4 v2 = e[(size_t)i2 * 32];
        float4 v3 = e[(size_t)i3 * 32];
        acc.x += (v0.x + v1.x) + (v2.x + v3.x);
        acc.y += (v0.y + v1.y) + (v2.y + v3.y);
        acc.z += (v0.z + v1.z) + (v2.z + v3.z);
        acc.w += (v0.w + v1.w) + (v2.w + v3.w);
    }
    for (; k < count; ++k) {
        float4 v0 = e[(size_t)sidx[wid][k] * 32];
        acc.x += v0.x; acc.y += v0.y; acc.z += v0.z; acc.w += v0.w;
    }

    const float inv = 1.0f / (float)(count > 0 ? count : 1);
    acc.x *= inv; acc.y *= inv; acc.z *= inv; acc.w *= inv;

    float* m = g_mean + ((size_t)y * BB + b) * KTOT + r * GG + lane * 4;
    *(float4*)m = acc;
}

// ---------------------------------------------------------------------------
// K-split SGEMM with fused fixed-order reduce:
//   g_part[s] = A[:, s*96:(s+1)*96] @ W[s*96:(s+1)*96, :]
//   last CTA per row tile (split-k semaphore) sums p0+p1+p2+p3 -> out.
// Tile BM=32 x BN=128, BK=32, 3 chunks; 128 threads; grid = 160 x 4 = 640.
// Warp w: rows w*8..w*8+7; lane: cols lane*4..+3 -> 16 f32x2 accs/thread.
// W staged with cp.async; A register-staged (transpose); double-buffered.
// ---------------------------------------------------------------------------
#define BM 32
#define BN 128
#define BK 32
#define KSPL (KTOT / NSPLIT)    // 96
#define NCHUNK (KSPL / BK)      // 3
#define APAD 8                  // A row stride 40 floats -> 16B-divisible

__device__ __forceinline__ unsigned long long fma2(unsigned long long a,
                                                   unsigned long long b,
                                                   unsigned long long c) {
    unsigned long long d;
    asm("fma.rn.f32x2 %0, %1, %2, %3;" : "=l"(d) : "l"(a), "l"(b), "l"(c));
    return d;
}
__device__ __forceinline__ unsigned long long dup2(float x) {
    unsigned long long d;
    unsigned int u = __float_as_uint(x);
    asm("mov.b64 %0, {%1, %1};" : "=l"(d) : "r"(u));
    return d;
}
__device__ __forceinline__ float2 unpk2(unsigned long long p) {
    unsigned int lo, hi;
    asm("mov.b64 {%0, %1}, %2;" : "=r"(lo), "=r"(hi) : "l"(p));
    return make_float2(__uint_as_float(lo), __uint_as_float(hi));
}
__device__ __forceinline__ void cp_async16(unsigned int smem_addr,
                                           const void* gptr) {
    asm volatile("cp.async.ca.shared.global [%0], [%1], 16;\n"
                 :: "r"(smem_addr), "l"(gptr));
}
__device__ __forceinline__ void cp_async_commit() {
    asm volatile("cp.async.commit_group;\n");
}
__device__ __forceinline__ void cp_async_wait0() {
    asm volatile("cp.async.wait_group 0;\n");
}

__global__ void __launch_bounds__(128) gemm_partial_kernel(float* __restrict__ out) {
    __shared__ __align__(16) float Ast[2][BK][BM + APAD];  // transposed A
    __shared__ __align__(16) float Ws[2][BK][BN];
    __shared__ int s_last;

    const int tid  = threadIdx.x;        // 0..127
    const int w    = tid >> 5;           // warp 0..3 -> rows w*8..w*8+7
    const int lane = tid & 31;           // cols lane*4..lane*4+3
    const int ksplit  = blockIdx.x & (NSPLIT - 1);
    const int tile    = blockIdx.x >> 2;
    const int rowbase = tile * BM;
    const int kbase   = ksplit * KSPL;

    unsigned long long acc[4][4];        // [rowpair][col]
    #pragma unroll
    for (int i = 0; i < 4; ++i)
        #pragma unroll
        for (int j = 0; j < 4; ++j) acc[i][j] = 0ull;

    const float* Ag = g_mean + (size_t)rowbase * KTOT + kbase;
    const float* Wg = g_weff + (size_t)kbase * BN;

    const int wrow = tid >> 5;           // 0..3   (k within chunk, +4 per j)
    const int wcol = (tid & 31) << 2;    // 0..124

    unsigned int ws_base[2];
    ws_base[0] = (unsigned int)__cvta_generic_to_shared(&Ws[0][0][0]);
    ws_base[1] = (unsigned int)__cvta_generic_to_shared(&Ws[1][0][0]);

    // prologue: stage chunk 0 (A: 2 float4/thread; W: 8 cp.async/thread)
    {
        #pragma unroll
        for (int j = 0; j < 2; ++j) {
            int l = tid + j * 128;
            int rr = l >> 3, kc = (l & 7) << 2;
            float4 pa = *(const float4*)(Ag + (size_t)rr * KTOT + kc);
            Ast[0][kc + 0][rr] = pa.x;
            Ast[0][kc + 1][rr] = pa.y;
            Ast[0][kc + 2][rr] = pa.z;
            Ast[0][kc + 3][rr] = pa.w;
        }
        #pragma unroll
        for (int j = 0; j < 8; ++j) {
            int kr = wrow + j * 4;       // 0..31
            cp_async16(ws_base[0] + (unsigned int)((kr * BN + wcol) * 4),
                       Wg + (size_t)kr * BN + wcol);
        }
        cp_async_commit();
        cp_async_wait0();
    }
    __syncthreads();

    for (int c = 0; c < NCHUNK; ++c) {
        const int buf = c & 1;
        const bool more = (c + 1 < NCHUNK);
        float4 pa0, pa1;
        if (more) {
            const int k0 = (c + 1) * BK;
            {
                int l = tid;
                pa0 = *(const float4*)(Ag + (size_t)(l >> 3) * KTOT + k0 + ((l & 7) << 2));
                l = tid + 128;
                pa1 = *(const float4*)(Ag + (size_t)(l >> 3) * KTOT + k0 + ((l & 7) << 2));
            }
            #pragma unroll
            for (int j = 0; j < 8; ++j) {
                int kr = wrow + j * 4;
                cp_async16(ws_base[buf ^ 1] + (unsigned int)((kr * BN + wcol) * 4),
                           Wg + (size_t)(k0 + kr) * BN + wcol);
            }
            cp_async_commit();
        }

        #pragma unroll
        for (int kk = 0; kk < BK; ++kk) {
            ulonglong2 aP0 = *(const ulonglong2*)&Ast[buf][kk][w * 8];      // rows 0-3
            ulonglong2 aP1 = *(const ulonglong2*)&Ast[buf][kk][w * 8 + 4];  // rows 4-7
            float4 w4 = *(const float4*)&Ws[buf][kk][lane * 4];
            unsigned long long wd0 = dup2(w4.x), wd1 = dup2(w4.y);
            unsigned long long wd2 = dup2(w4.z), wd3 = dup2(w4.w);

            acc[0][0] = fma2(aP0.x, wd0, acc[0][0]);
            acc[0][1] = fma2(aP0.x, wd1, acc[0][1]);
            acc[0][2] = fma2(aP0.x, wd2, acc[0][2]);
            acc[0][3] = fma2(aP0.x, wd3, acc[0][3]);
            acc[1][0] = fma2(aP0.y, wd0, acc[1][0]);
            acc[1][1] = fma2(aP0.y, wd1, acc[1][1]);
            acc[1][2] = fma2(aP0.y, wd2, acc[1][2]);
            acc[1][3] = fma2(aP0.y, wd3, acc[1][3]);
            acc[2][0] = fma2(aP1.x, wd0, acc[2][0]);
            acc[2][1] = fma2(aP1.x, wd1, acc[2][1]);
            acc[2][2] = fma2(aP1.x, wd2, acc[2][2]);
            acc[2][3] = fma2(aP1.x, wd3, acc[2][3]);
            acc[3][0] = fma2(aP1.y, wd0, acc[3][0]);
            acc[3][1] = fma2(aP1.y, wd1, acc[3][1]);
            acc[3][2] = fma2(aP1.y, wd2, acc[3][2]);
            acc[3][3] = fma2(aP1.y, wd3, acc[3][3]);
        }

        if (more) {
            const int nbuf = buf ^ 1;
            {
                int l = tid;
                int rr = l >> 3, kc = (l & 7) << 2;
                Ast[nbuf][kc + 0][rr] = pa0.x;
                Ast[nbuf][kc + 1][rr] = pa0.y;
                Ast[nbuf][kc + 2][rr] = pa0.z;
                Ast[nbuf][kc + 3][rr] = pa0.w;
                l = tid + 128;
                rr = l >> 3; kc = (l & 7) << 2;
                Ast[nbuf][kc + 0][rr] = pa1.x;
                Ast[nbuf][kc + 1][rr] = pa1.y;
                Ast[nbuf][kc + 2][rr] = pa1.z;
                Ast[nbuf][kc + 3][rr] = pa1.w;
            }
            cp_async_wait0();
            __syncthreads();
        }
    }

    // write partial
    float* p = g_part[ksplit] + (size_t)(rowbase + w * 8) * BN + lane * 4;
    #pragma unroll
    for (int rp = 0; rp < 4; ++rp) {
        float2 c0 = unpk2(acc[rp][0]);
        float2 c1 = unpk2(acc[rp][1]);
        float2 c2 = unpk2(acc[rp][2]);
        float2 c3 = unpk2(acc[rp][3]);
        *(float4*)(p + (size_t)(2 * rp) * BN)     = make_float4(c0.x, c1.x, c2.x, c3.x);
        *(float4*)(p + (size_t)(2 * rp + 1) * BN) = make_float4(c0.y, c1.y, c2.y, c3.y);
    }

    // split-k semaphore: last CTA for this row tile reduces in FIXED order
    __threadfence();
    if (tid == 0) {
        int old = atomicAdd(&g_sem[tile], 1);
        s_last = (old == NSPLIT - 1) ? 1 : 0;
    }
    __syncthreads();
    if (s_last) {
        __threadfence();   // acquire: partials from other CTAs visible
        const size_t base4 = (size_t)rowbase * (BN / 4);   // float4 units
        const float4* q0 = (const float4*)g_part[0] + base4;
        const float4* q1 = (const float4*)g_part[1] + base4;
        const float4* q2 = (const float4*)g_part[2] + base4;
        const float4* q3 = (const float4*)g_part[3] + base4;
        float4* o = (float4*)out + base4;
        #pragma unroll
        for (int j = 0; j < 8; ++j) {
            int l = tid + j * 128;       // 0..1023 float4s in tile
            float4 a = q0[l], bq = q1[l], cq = q2[l], dq = q3[l];
            float4 rv;
            rv.x = ((a.x + bq.x) + cq.x) + dq.x;
            rv.y = ((a.y + bq.y) + cq.y) + dq.y;
            rv.z = ((a.z + bq.z) + cq.z) + dq.z;
            rv.w = ((a.w + bq.w) + cq.w) + dq.w;
            o[l] = rv;
        }
    }
}

// ---------------------------------------------------------------------------
// kernel_launch: [weff-build + sem-zero + warp-gather] -> K-split GEMM+reduce
// ---------------------------------------------------------------------------
extern "C" void kernel_launch(void* const* d_in, const int* in_sizes, int n_in,
                              void* d_out, int out_size) {
    const float* emb   = (const float*)d_in[0];
    const float* Wrel  = (const float*)d_in[1];
    const float* Wcite = (const float*)d_in[2];
    const void*  nbr   = d_in[3];
    const void*  cnt   = d_in[4];
    float* out = (float*)d_out;

    gather_mean_kernel<<<NWEFF_BLK + (YY * RR * BB) / 8, 256>>>(emb, nbr, cnt, Wrel, Wcite);

    gemm_partial_kernel<<<NTILE * NSPLIT, 128>>>(out);
}